// round 2
// baseline (speedup 1.0000x reference)
#include <cuda_runtime.h>
#include <cuda_fp16.h>
#include <cstdint>

// ---------------------------------------------------------------------------
// Problem constants
// ---------------------------------------------------------------------------
#define N_IMG  16
#define CI     256
#define CO     256
#define HW     56
#define KTAP   13
#define PAD    6
#define HP     68           // 56 + 12
#define WPAD   76           // 64 + 12 (w tile 0..63, s up to 12)

// Scratch (device globals; no cudaMalloc allowed)
__device__ __half g_xp[(size_t)N_IMG * HP * WPAD * CI];     // [n][hp][wp][ci]  ~42 MB
__device__ __half g_wt[(size_t)KTAP * KTAP * CO * CI];      // [tap][co][ci]    ~22 MB

// ---------------------------------------------------------------------------
// Helpers (arch-neutral PTX only: sm_80-class mma.sync / ldmatrix / cp.async)
// ---------------------------------------------------------------------------
__device__ __forceinline__ uint32_t smem_u32(const void* p) {
    uint32_t a;
    asm("{ .reg .u64 t; cvta.to.shared.u64 t, %1; cvt.u32.u64 %0, t; }" : "=r"(a) : "l"(p));
    return a;
}
__device__ __forceinline__ uint32_t swz(uint32_t off) {      // SW128: cols[4:6] ^= rows[7:9]
    return off ^ ((off >> 3) & 0x70);
}
__device__ __forceinline__ void cp16(uint32_t dst, const void* src) {
    asm volatile("cp.async.cg.shared.global [%0], [%1], 16;" :: "r"(dst), "l"(src) : "memory");
}
#define CP_COMMIT() asm volatile("cp.async.commit_group;" ::: "memory")
#define CP_WAIT(n)  asm volatile("cp.async.wait_group %0;" :: "n"(n) : "memory")

__device__ __forceinline__ void ldsm4(uint32_t* r, uint32_t addr) {
    asm volatile("ldmatrix.sync.aligned.m8n8.x4.shared.b16 {%0,%1,%2,%3}, [%4];"
                 : "=r"(r[0]), "=r"(r[1]), "=r"(r[2]), "=r"(r[3]) : "r"(addr));
}
__device__ __forceinline__ void mma16816(float* d, const uint32_t* a, const uint32_t* b) {
    asm volatile(
        "mma.sync.aligned.m16n8k16.row.col.f32.f16.f16.f32 "
        "{%0,%1,%2,%3}, {%4,%5,%6,%7}, {%8,%9}, {%0,%1,%2,%3};"
        : "+f"(d[0]), "+f"(d[1]), "+f"(d[2]), "+f"(d[3])
        : "r"(a[0]), "r"(a[1]), "r"(a[2]), "r"(a[3]), "r"(b[0]), "r"(b[1]));
}

// ---------------------------------------------------------------------------
// Prepass 1: pad + transpose input NCHW f32 -> padded NHWC f16
// grid = N_IMG*HP, 256 threads (one ci each)
// ---------------------------------------------------------------------------
__global__ void pad_input_kernel(const float* __restrict__ x) {
    const int nb = blockIdx.x;
    const int n  = nb / HP;
    const int hp = nb % HP;
    const int ci = threadIdx.x;
    const int h  = hp - PAD;
    const bool hv = (h >= 0) && (h < HW);
    const float* xrow = x + ((size_t)(n * CI + ci) * HW + (hv ? h : 0)) * HW;
    __half* dst = g_xp + ((size_t)(n * HP + hp) * WPAD) * CI + ci;
    #pragma unroll 4
    for (int wp = 0; wp < WPAD; ++wp) {
        const int w = wp - PAD;
        float v = 0.f;
        if (hv && w >= 0 && w < HW) v = xrow[w];
        dst[(size_t)wp * CI] = __float2half(v);
    }
}

// ---------------------------------------------------------------------------
// Prepass 2: weights (co,ci,13,13) f32 -> [tap][co][ci] f16
// ---------------------------------------------------------------------------
__global__ void conv_weight_kernel(const float* __restrict__ w) {
    const int id = blockIdx.x * 256 + threadIdx.x;   // co*256 + ci
    const int co = id >> 8;
    const int ci = id & 255;
    const float* src = w + (size_t)id * (KTAP * KTAP);
    __half* dst = g_wt + (size_t)co * CI + ci;
    #pragma unroll 13
    for (int t = 0; t < KTAP * KTAP; ++t)
        dst[(size_t)t * (CO * CI)] = __float2half(src[t]);
}

// ---------------------------------------------------------------------------
// Main: implicit-GEMM conv + BN + SiLU via mma.sync (m16n8k16 f16->f32)
// CTA tile: M=128 co x N=128 spatial (2 h-rows x 64 w) x K-stage 64
// K loop: 169 taps x 4 ci-chunks = 676 iters, cp.async double buffer
// grid = (448, 2): x = n*28 + htile, y = co block
// ---------------------------------------------------------------------------
#define A_BYTES     16384          // 128 rows x 128B
#define STAGE_BYTES 32768          // A + B
#define SMEM_DYN    (2 * STAGE_BYTES + 1024)

__global__ void __launch_bounds__(256) conv_main_kernel(
    const float* __restrict__ gamma, const float* __restrict__ beta,
    const float* __restrict__ rmean, const float* __restrict__ rvar,
    float* __restrict__ out)
{
    extern __shared__ char smem_raw[];
    const uint32_t base = (smem_u32(smem_raw) + 1023u) & ~1023u;

    const int tid = threadIdx.x;
    const int l   = tid & 31;
    const int wid = tid >> 5;
    const int st  = blockIdx.x;
    const int cob = blockIdx.y;
    const int n   = st / 28;
    const int h0  = (st % 28) * 2;

    // ---- cp.async geometry: 8 chunks(16B) per 128B row, 256 thr -> 32 rows/pass
    const int c16  = tid & 7;
    const int row0 = tid >> 3;
    const char* a_src[4]; const char* b_src[4];
    uint32_t a_dst[4], b_dst[4];
    #pragma unroll
    for (int i = 0; i < 4; ++i) {
        const int rw = row0 + 32 * i;
        a_src[i] = (const char*)g_wt + (size_t)(cob * 128 + rw) * (CI * 2) + c16 * 16;
        a_dst[i] = swz((uint32_t)(rw * 128 + c16 * 16));
        const int jr = rw >> 6, wc = rw & 63;
        b_src[i] = (const char*)g_xp + (size_t)((n * HP + h0 + jr) * WPAD + wc) * (CI * 2) + c16 * 16;
        b_dst[i] = swz((uint32_t)(rw * 128 + c16 * 16)) + A_BYTES;
    }

    auto issue = [&](int i2, int stage) {
        const int kc = i2 & 3, t = i2 >> 2;
        const int r = t / 13, s = t - r * 13;
        const size_t aoff = (size_t)t * (CO * CI * 2) + (size_t)kc * 128;
        const size_t boff = (size_t)(r * WPAD + s) * (CI * 2) + (size_t)kc * 128;
        const uint32_t sb = base + stage * STAGE_BYTES;
        #pragma unroll
        for (int i = 0; i < 4; ++i) cp16(sb + a_dst[i], a_src[i] + aoff);
        #pragma unroll
        for (int i = 0; i < 4; ++i) cp16(sb + b_dst[i], b_src[i] + boff);
    };

    // ---- MMA fragment geometry (warp grid 4x2, warp tile 32(M) x 64(N))
    const int wm = wid >> 1, wn = wid & 1;
    const int m0 = wm * 32, n0 = wn * 64;
    int arow[2]; uint32_t axor[2];
    int brow[4]; uint32_t bxor[4];
    const uint32_t hi_a = (uint32_t)((l >> 4) << 4);          // 16B chunk select
    const uint32_t hi_b = (uint32_t)(((l >> 3) & 1) << 4);
    #pragma unroll
    for (int mt = 0; mt < 2; ++mt) {
        const int r = m0 + 16 * mt + (l & 15);
        arow[mt] = r; axor[mt] = (uint32_t)((r & 7) << 4);
    }
    #pragma unroll
    for (int bt = 0; bt < 4; ++bt) {
        const int r = n0 + 16 * bt + (l & 7) + ((l >> 4) << 3);
        brow[bt] = r; bxor[bt] = (uint32_t)((r & 7) << 4);
    }

    float acc[2][8][4];
    #pragma unroll
    for (int i = 0; i < 2; ++i)
        #pragma unroll
        for (int j = 0; j < 8; ++j)
            #pragma unroll
            for (int k = 0; k < 4; ++k) acc[i][j][k] = 0.f;

    // ---- mainloop: 676 K-stages, double-buffered
    issue(0, 0); CP_COMMIT();
    #pragma unroll 1
    for (int i = 0; i < 676; ++i) {
        const int stage = i & 1;
        if (i < 675) { issue(i + 1, stage ^ 1); CP_COMMIT(); CP_WAIT(1); }
        else         { CP_WAIT(0); }
        __syncthreads();
        const uint32_t ab = base + stage * STAGE_BYTES;
        const uint32_t bb = ab + A_BYTES;
        #pragma unroll
        for (int kk = 0; kk < 4; ++kk) {
            uint32_t a[2][4];
            #pragma unroll
            for (int mt = 0; mt < 2; ++mt)
                ldsm4(a[mt], ab + arow[mt] * 128 + (((uint32_t)kk * 32 + hi_a) ^ axor[mt]));
            #pragma unroll
            for (int bt = 0; bt < 4; ++bt) {
                uint32_t b[4];
                ldsm4(b, bb + brow[bt] * 128 + (((uint32_t)kk * 32 + hi_b) ^ bxor[bt]));
                #pragma unroll
                for (int mt = 0; mt < 2; ++mt) {
                    mma16816(acc[mt][2 * bt],     a[mt], b);
                    mma16816(acc[mt][2 * bt + 1], a[mt], b + 2);
                }
            }
        }
        __syncthreads();
    }

    // ---- epilogue: BN + SiLU, registers -> NCHW fp32
    #pragma unroll
    for (int mt = 0; mt < 2; ++mt) {
        #pragma unroll
        for (int hf = 0; hf < 2; ++hf) {
            const int co = cob * 128 + m0 + 16 * mt + 8 * hf + (l >> 2);
            const float sc = gamma[co] * rsqrtf(rvar[co] + 1e-5f);
            const float sh = beta[co] - rmean[co] * sc;
            float* op = out + (size_t)(n * CO + co) * (HW * HW);
            #pragma unroll
            for (int nt = 0; nt < 8; ++nt) {
                #pragma unroll
                for (int e = 0; e < 2; ++e) {
                    const int c = n0 + 8 * nt + 2 * (l & 3) + e;
                    const int w = c & 63;
                    if (w < HW) {
                        const int h = h0 + (c >> 6);
                        const float y = acc[mt][nt][hf * 2 + e] * sc + sh;
                        op[h * HW + w] = y / (1.f + __expf(-y));
                    }
                }
            }
        }
    }
}

// ---------------------------------------------------------------------------
// kernel_launch
// ---------------------------------------------------------------------------
extern "C" void kernel_launch(void* const* d_in, const int* in_sizes, int n_in,
                              void* d_out, int out_size)
{
    const float* x     = (const float*)d_in[0];
    const float* w     = (const float*)d_in[1];
    const float* gamma = (const float*)d_in[2];
    const float* beta  = (const float*)d_in[3];
    const float* rmean = (const float*)d_in[4];
    const float* rvar  = (const float*)d_in[5];
    float* out = (float*)d_out;

    cudaFuncSetAttribute(conv_main_kernel,
                         cudaFuncAttributeMaxDynamicSharedMemorySize, SMEM_DYN);

    pad_input_kernel<<<N_IMG * HP, 256>>>(x);
    conv_weight_kernel<<<(CO * CI) / 256, 256>>>(w);
    conv_main_kernel<<<dim3(N_IMG * 28, 2), 256, SMEM_DYN>>>(gamma, beta, rmean, rvar, out);
}

// round 3
// speedup vs baseline: 1.0852x; 1.0852x over previous
#include <cuda_runtime.h>
#include <cuda_fp16.h>
#include <cstdint>

// ---------------------------------------------------------------------------
// Problem constants
// ---------------------------------------------------------------------------
#define N_IMG  16
#define CI     256
#define CO     256
#define HW     56
#define KTAP   13
#define PAD    6
#define HP     68           // 56 + 12
#define WPAD   76           // 64 + 12 (w tile 0..63, s up to 12)

// Scratch (device globals; no cudaMalloc allowed)
__device__ __half g_xp[(size_t)N_IMG * HP * WPAD * CI];     // [n][hp][wp][ci]  ~42 MB
__device__ __half g_wt[(size_t)KTAP * KTAP * CO * CI];      // [tap][co][ci]    ~22 MB

// ---------------------------------------------------------------------------
// Helpers (arch-neutral PTX only: sm_80-class mma.sync / ldmatrix / cp.async)
// ---------------------------------------------------------------------------
__device__ __forceinline__ uint32_t smem_u32(const void* p) {
    uint32_t a;
    asm("{ .reg .u64 t; cvta.to.shared.u64 t, %1; cvt.u32.u64 %0, t; }" : "=r"(a) : "l"(p));
    return a;
}
__device__ __forceinline__ uint32_t swz(uint32_t off) {      // SW128: cols[4:6] ^= rows[7:9]
    return off ^ ((off >> 3) & 0x70);
}
__device__ __forceinline__ void cp16(uint32_t dst, const void* src) {
    asm volatile("cp.async.cg.shared.global [%0], [%1], 16;" :: "r"(dst), "l"(src) : "memory");
}
#define CP_COMMIT() asm volatile("cp.async.commit_group;" ::: "memory")
#define CP_WAIT(n)  asm volatile("cp.async.wait_group %0;" :: "n"(n) : "memory")

__device__ __forceinline__ void ldsm4(uint32_t* r, uint32_t addr) {
    asm volatile("ldmatrix.sync.aligned.m8n8.x4.shared.b16 {%0,%1,%2,%3}, [%4];"
                 : "=r"(r[0]), "=r"(r[1]), "=r"(r[2]), "=r"(r[3]) : "r"(addr));
}
__device__ __forceinline__ void mma16816(float* d, const uint32_t* a, const uint32_t* b) {
    asm volatile(
        "mma.sync.aligned.m16n8k16.row.col.f32.f16.f16.f32 "
        "{%0,%1,%2,%3}, {%4,%5,%6,%7}, {%8,%9}, {%0,%1,%2,%3};"
        : "+f"(d[0]), "+f"(d[1]), "+f"(d[2]), "+f"(d[3])
        : "r"(a[0]), "r"(a[1]), "r"(a[2]), "r"(a[3]), "r"(b[0]), "r"(b[1]));
}

// ---------------------------------------------------------------------------
// Prepass 1: pad + transpose input NCHW f32 -> padded NHWC f16
// ---------------------------------------------------------------------------
__global__ void pad_input_kernel(const float* __restrict__ x) {
    const int nb = blockIdx.x;
    const int n  = nb / HP;
    const int hp = nb % HP;
    const int ci = threadIdx.x;
    const int h  = hp - PAD;
    const bool hv = (h >= 0) && (h < HW);
    const float* xrow = x + ((size_t)(n * CI + ci) * HW + (hv ? h : 0)) * HW;
    __half* dst = g_xp + ((size_t)(n * HP + hp) * WPAD) * CI + ci;
    #pragma unroll 4
    for (int wp = 0; wp < WPAD; ++wp) {
        const int w = wp - PAD;
        float v = 0.f;
        if (hv && w >= 0 && w < HW) v = xrow[w];
        dst[(size_t)wp * CI] = __float2half(v);
    }
}

// ---------------------------------------------------------------------------
// Prepass 2: weights (co,ci,13,13) f32 -> [tap][co][ci] f16
// ---------------------------------------------------------------------------
__global__ void conv_weight_kernel(const float* __restrict__ w) {
    const int id = blockIdx.x * 256 + threadIdx.x;   // co*256 + ci
    const int co = id >> 8;
    const int ci = id & 255;
    const float* src = w + (size_t)id * (KTAP * KTAP);
    __half* dst = g_wt + (size_t)co * CI + ci;
    #pragma unroll 13
    for (int t = 0; t < KTAP * KTAP; ++t)
        dst[(size_t)t * (CO * CI)] = __float2half(src[t]);
}

// ---------------------------------------------------------------------------
// Main: implicit-GEMM conv + BN + SiLU via mma.sync (m16n8k16 f16->f32)
// CTA tile: M=128 co x N=128 spatial (2 h-rows x 64 w) x K-stage 64
// K loop: 169 taps x 4 ci-chunks = 676 iters, 3-stage cp.async pipeline,
// ONE __syncthreads per iteration.
// grid = (448, 2): x = n*28 + htile, y = co block
// ---------------------------------------------------------------------------
#define A_BYTES     16384          // 128 rows x 128B
#define STAGE_BYTES 32768          // A + B
#define NSTAGE      3
#define SMEM_DYN    (NSTAGE * STAGE_BYTES + 1024)

__global__ void __launch_bounds__(256, 2) conv_main_kernel(
    const float* __restrict__ gamma, const float* __restrict__ beta,
    const float* __restrict__ rmean, const float* __restrict__ rvar,
    float* __restrict__ out)
{
    extern __shared__ char smem_raw[];
    const uint32_t base = (smem_u32(smem_raw) + 1023u) & ~1023u;

    const int tid = threadIdx.x;
    const int l   = tid & 31;
    const int wid = tid >> 5;
    const int st  = blockIdx.x;
    const int cob = blockIdx.y;
    const int n   = st / 28;
    const int h0  = (st % 28) * 2;

    // ---- cp.async geometry: 8 chunks(16B) per 128B row, 256 thr -> 32 rows/pass
    const int c16  = tid & 7;
    const int row0 = tid >> 3;
    const char* a_src[4]; const char* b_src[4];
    uint32_t a_dst[4], b_dst[4];
    #pragma unroll
    for (int i = 0; i < 4; ++i) {
        const int rw = row0 + 32 * i;
        a_src[i] = (const char*)g_wt + (size_t)(cob * 128 + rw) * (CI * 2) + c16 * 16;
        a_dst[i] = swz((uint32_t)(rw * 128 + c16 * 16));
        const int jr = rw >> 6, wc = rw & 63;
        b_src[i] = (const char*)g_xp + (size_t)((n * HP + h0 + jr) * WPAD + wc) * (CI * 2) + c16 * 16;
        b_dst[i] = swz((uint32_t)(rw * 128 + c16 * 16)) + A_BYTES;
    }

    // Producer-side counters (strength-reduced; no division in the loop)
    int p_kc = 0;                 // ci-chunk 0..3
    size_t p_woff = 0;            // tap * CO*CI*2
    size_t p_xoff = 0;            // (r*WPAD+s) * CI*2
    int p_s = 0;                  // tap column 0..12
    int p_ws = 0;                 // write stage 0..NSTAGE-1

    auto issue = [&]() {
        const uint32_t sb = base + (uint32_t)p_ws * STAGE_BYTES;
        const size_t aoff = p_woff + (size_t)p_kc * 128;
        const size_t boff = p_xoff + (size_t)p_kc * 128;
        #pragma unroll
        for (int i = 0; i < 4; ++i) cp16(sb + a_dst[i], a_src[i] + aoff);
        #pragma unroll
        for (int i = 0; i < 4; ++i) cp16(sb + b_dst[i], b_src[i] + boff);
        CP_COMMIT();
        if (++p_ws == NSTAGE) p_ws = 0;
        if (++p_kc == 4) {
            p_kc = 0;
            p_woff += (size_t)CO * CI * 2;
            if (++p_s == KTAP) { p_s = 0; p_xoff += (size_t)(WPAD - (KTAP - 1)) * CI * 2; }
            else               { p_xoff += (size_t)CI * 2; }
        }
    };

    // ---- MMA fragment geometry (warp grid 4x2, warp tile 32(M) x 64(N))
    const int wm = wid >> 1, wn = wid & 1;
    const int m0 = wm * 32, n0 = wn * 64;
    int arow[2]; uint32_t axor[2];
    int brow[4]; uint32_t bxor[4];
    const uint32_t hi_a = (uint32_t)((l >> 4) << 4);          // 16B chunk select
    const uint32_t hi_b = (uint32_t)(((l >> 3) & 1) << 4);
    #pragma unroll
    for (int mt = 0; mt < 2; ++mt) {
        const int r = m0 + 16 * mt + (l & 15);
        arow[mt] = r; axor[mt] = (uint32_t)((r & 7) << 4);
    }
    #pragma unroll
    for (int bt = 0; bt < 4; ++bt) {
        const int r = n0 + 16 * bt + (l & 7) + ((l >> 4) << 3);
        brow[bt] = r; bxor[bt] = (uint32_t)((r & 7) << 4);
    }

    float acc[2][8][4];
    #pragma unroll
    for (int i = 0; i < 2; ++i)
        #pragma unroll
        for (int j = 0; j < 8; ++j)
            #pragma unroll
            for (int k = 0; k < 4; ++k) acc[i][j][k] = 0.f;

    auto compute = [&](int stage) {
        const uint32_t ab = base + (uint32_t)stage * STAGE_BYTES;
        const uint32_t bb = ab + A_BYTES;
        #pragma unroll
        for (int kk = 0; kk < 4; ++kk) {
            uint32_t a[2][4];
            #pragma unroll
            for (int mt = 0; mt < 2; ++mt)
                ldsm4(a[mt], ab + arow[mt] * 128 + (((uint32_t)kk * 32 + hi_a) ^ axor[mt]));
            #pragma unroll
            for (int bt = 0; bt < 4; ++bt) {
                uint32_t b[4];
                ldsm4(b, bb + brow[bt] * 128 + (((uint32_t)kk * 32 + hi_b) ^ bxor[bt]));
                #pragma unroll
                for (int mt = 0; mt < 2; ++mt) {
                    mma16816(acc[mt][2 * bt],     a[mt], b);
                    mma16816(acc[mt][2 * bt + 1], a[mt], b + 2);
                }
            }
        }
    };

    // ---- mainloop: 676 K-stages, 3-stage pipeline, one barrier per iter.
    // Stage written at iter i (stage (i+2)%3) was consumed at iter i-1; the
    // barrier at the top of iter i orders that consumption before the write.
    issue();   // stage 0  (iter 0 data)
    issue();   // stage 1  (iter 1 data)
    int rs = 0;                    // read stage
    #pragma unroll 1
    for (int i = 0; i < 674; ++i) {
        CP_WAIT(1);                // group i complete (one newer may be in flight)
        __syncthreads();
        issue();                   // iter i+2 data -> stage (i+2)%3
        compute(rs);
        if (++rs == NSTAGE) rs = 0;
    }
    // Tail: groups 674, 675 already committed; drain everything once.
    CP_WAIT(0);
    __syncthreads();
    compute(rs); if (++rs == NSTAGE) rs = 0;   // iter 674
    compute(rs);                                // iter 675

    // ---- epilogue: BN + SiLU, registers -> NCHW fp32
    #pragma unroll
    for (int mt = 0; mt < 2; ++mt) {
        #pragma unroll
        for (int hf = 0; hf < 2; ++hf) {
            const int co = cob * 128 + m0 + 16 * mt + 8 * hf + (l >> 2);
            const float sc = gamma[co] * rsqrtf(rvar[co] + 1e-5f);
            const float sh = beta[co] - rmean[co] * sc;
            float* op = out + (size_t)(n * CO + co) * (HW * HW);
            #pragma unroll
            for (int nt = 0; nt < 8; ++nt) {
                #pragma unroll
                for (int e = 0; e < 2; ++e) {
                    const int c = n0 + 8 * nt + 2 * (l & 3) + e;
                    const int w = c & 63;
                    if (w < HW) {
                        const int h = h0 + (c >> 6);
                        const float y = acc[mt][nt][hf * 2 + e] * sc + sh;
                        op[h * HW + w] = y / (1.f + __expf(-y));
                    }
                }
            }
        }
    }
}

// ---------------------------------------------------------------------------
// kernel_launch
// ---------------------------------------------------------------------------
extern "C" void kernel_launch(void* const* d_in, const int* in_sizes, int n_in,
                              void* d_out, int out_size)
{
    const float* x     = (const float*)d_in[0];
    const float* w     = (const float*)d_in[1];
    const float* gamma = (const float*)d_in[2];
    const float* beta  = (const float*)d_in[3];
    const float* rmean = (const float*)d_in[4];
    const float* rvar  = (const float*)d_in[5];
    float* out = (float*)d_out;

    cudaFuncSetAttribute(conv_main_kernel,
                         cudaFuncAttributeMaxDynamicSharedMemorySize, SMEM_DYN);

    pad_input_kernel<<<N_IMG * HP, 256>>>(x);
    conv_weight_kernel<<<(CO * CI) / 256, 256>>>(w);
    conv_main_kernel<<<dim3(N_IMG * 28, 2), 256, SMEM_DYN>>>(gamma, beta, rmean, rvar, out);
}